// round 14
// baseline (speedup 1.0000x reference)
#include <cuda_runtime.h>
#include <cuda_bf16.h>

#define N_NODES 10000
#define N_EDGES 320000
#define HID 256
#define L_LEN 140
#define C_IN 5
#define C_MID 64
#define IN_FEATS (C_MID * L_LEN)   // 8960
#define EPS 1e-5f

// d_out layout: [out (N*2)][cnn1 (N*64*140)][cnn2 (N*64*140)][fin (N*256)]
#define CNN1_OFF (N_NODES * 2)
#define CNN2_OFF (CNN1_OFF + N_NODES * C_MID * L_LEN)
#define FIN_OFF  (CNN2_OFF + N_NODES * C_MID * L_LEN)

// weight (transposed, split) buffer: layer0 512x8960, layers1-3 512x256
#define W_L0_ELEMS (512 * IN_FEATS)
#define W_REST_ELEMS (512 * HID)
#define W_TOTAL (W_L0_ELEMS + 3 * W_REST_ELEMS)

// extra tail blocks that process edges inside conv kernels
#define EDGE_BLOCKS ((N_EDGES + 255) / 256)   // 1250

typedef unsigned long long ull;

// ---------------- f32x2 helpers ----------------
__device__ __forceinline__ ull pkdup(float x) {
    unsigned int u = __float_as_uint(x);
    ull r;
    asm("mov.b64 %0, {%1, %1};" : "=l"(r) : "r"(u));
    return r;
}
__device__ __forceinline__ void ffma2(ull& d, ull a, ull b) {
    asm("fma.rn.f32x2 %0, %1, %2, %0;" : "+l"(d) : "l"(a), "l"(b));
}
__device__ __forceinline__ void unpk(ull v, float& lo, float& hi) {
    unsigned int a, b;
    asm("mov.b64 {%0, %1}, %2;" : "=r"(a), "=r"(b) : "l"(v));
    lo = __uint_as_float(a);
    hi = __uint_as_float(b);
}
__device__ __forceinline__ void lds2w(ull& p0, ull& p1, unsigned int addr) {
    asm volatile("ld.shared.v2.b64 {%0, %1}, [%2];" : "=l"(p0), "=l"(p1) : "r"(addr));
}
__device__ __forceinline__ void sts64(unsigned int addr, ull v) {
    asm volatile("st.shared.b64 [%0], %1;" :: "r"(addr), "l"(v));
}
__device__ __forceinline__ unsigned int smem_u32(const void* p) {
    unsigned int a;
    asm("{ .reg .u64 t; cvta.to.shared.u64 t, %1; cvt.u32.u64 %0, t; }" : "=r"(a) : "l"(p));
    return a;
}

// ---------------- mma.sync / ldmatrix / cp.async helpers ----------------
#define LDSM4(r, addr) \
    asm volatile("ldmatrix.sync.aligned.m8n8.x4.shared.b16 {%0,%1,%2,%3}, [%4];" \
                 : "=r"((r)[0]), "=r"((r)[1]), "=r"((r)[2]), "=r"((r)[3]) : "r"(addr))

#define MMA16816(d, a, b0, b1) \
    asm volatile("mma.sync.aligned.m16n8k16.row.col.f32.bf16.bf16.f32 " \
                 "{%0,%1,%2,%3}, {%4,%5,%6,%7}, {%8,%9}, {%0,%1,%2,%3};" \
                 : "+f"((d)[0]), "+f"((d)[1]), "+f"((d)[2]), "+f"((d)[3]) \
                 : "r"((a)[0]), "r"((a)[1]), "r"((a)[2]), "r"((a)[3]), \
                   "r"(b0), "r"(b1))

#define CP16(daddr, gptr) \
    asm volatile("cp.async.cg.shared.global [%0], [%1], 16;" \
                 :: "r"(daddr), "l"(gptr))

// ---------------- scratch (static device memory; no allocs) ----------------
__device__ float g_h [N_NODES * HID];
__device__ float g_h2[N_NODES * HID];
__device__ float g_hn[N_NODES * HID];
__device__ float g_hs[N_NODES * HID];
__device__ float g_z [N_NODES * C_MID];
__device__ float g_sum[HID];
__device__ float g_sq [HID];
__device__ float g_denom[N_NODES];
__device__ int   g_deg[N_NODES];
__device__ int   g_off[N_NODES + 1];
__device__ int   g_pos[N_NODES];
__device__ int   g_csr[N_EDGES];
__device__ __nv_bfloat16 g_Ahi[N_NODES * IN_FEATS];
__device__ __nv_bfloat16 g_Alo[N_NODES * IN_FEATS];
__device__ __nv_bfloat16 g_Whi[W_TOTAL];
__device__ __nv_bfloat16 g_Wlo[W_TOTAL];

// ---------------- small utility kernels ----------------
__global__ void zero_stats_kernel() {
    int t = threadIdx.x;
    g_sum[t] = 0.f;
    g_sq[t]  = 0.f;
}
__global__ void zero_deg_kernel() {
    int i = blockIdx.x * blockDim.x + threadIdx.x;
    if (i < N_NODES) g_deg[i] = 0;
}

// ---------------- conv1 + fused per-channel stats + tail-block degree count ----------------
__global__ __launch_bounds__(256) void conv1_kernel(
    const float* __restrict__ x, const float* __restrict__ w,
    const float* __restrict__ bias, float* __restrict__ out,
    const int* __restrict__ edges)
{
    __shared__ float sx[C_IN * L_LEN];
    __shared__ float sw[C_MID * C_IN];
    __shared__ float sb[C_MID];
    int n = blockIdx.x, t = threadIdx.x;
    if (n >= N_NODES) {
        int e = (n - N_NODES) * 256 + t;
        if (e < N_EDGES) atomicAdd(&g_deg[edges[2 * e + 1]], 1);
        return;
    }
    int warp = t >> 5, lane = t & 31;
    for (int i = t; i < C_IN * L_LEN; i += 256) sx[i] = x[(size_t)n * C_IN * L_LEN + i];
    for (int i = t; i < C_MID * C_IN; i += 256) sw[i] = w[i];
    if (t < C_MID) sb[t] = bias[t];
    __syncthreads();
#pragma unroll
    for (int j = 0; j < 8; j++) {
        int o = warp * 8 + j;
        float w0 = sw[o * C_IN + 0], w1 = sw[o * C_IN + 1], w2 = sw[o * C_IN + 2];
        float w3 = sw[o * C_IN + 3], w4 = sw[o * C_IN + 4];
        float bb = sb[o];
        float s = 0.f, q = 0.f;
#pragma unroll
        for (int i = 0; i < 5; i++) {
            int l = lane + 32 * i;
            if (l < L_LEN) {
                float val = bb + w0 * sx[l] + w1 * sx[L_LEN + l] + w2 * sx[2 * L_LEN + l]
                               + w3 * sx[3 * L_LEN + l] + w4 * sx[4 * L_LEN + l];
                out[(size_t)n * IN_FEATS + o * L_LEN + l] = val;
                s += val;
                q += val * val;
            }
        }
#pragma unroll
        for (int off = 16; off > 0; off >>= 1) {
            s += __shfl_down_sync(0xffffffffu, s, off);
            q += __shfl_down_sync(0xffffffffu, q, off);
        }
        if (lane == 0) {
            atomicAdd(&g_sum[o], s);
            atomicAdd(&g_sq[o],  q);
        }
    }
}

// ---------------- channel BN + relu (+residual) in-place; optional bf16 hi/lo split out ----------------
__global__ void bn_chan_apply_kernel(
    float4* __restrict__ x, const float4* __restrict__ res,
    const float* __restrict__ gam, const float* __restrict__ bet,
    __nv_bfloat162* __restrict__ ahi, __nv_bfloat162* __restrict__ alo, int soff)
{
    const float invc = 1.0f / ((float)N_NODES * L_LEN);
    const int total4 = N_NODES * C_MID * (L_LEN / 4);
    for (int idx = blockIdx.x * blockDim.x + threadIdx.x; idx < total4;
         idx += gridDim.x * blockDim.x) {
        int ch = (idx / (L_LEN / 4)) & (C_MID - 1);
        float m   = g_sum[soff + ch] * invc;
        float var = g_sq[soff + ch] * invc - m * m;
        float sc  = rsqrtf(var + EPS) * gam[ch];
        float sh  = bet[ch] - m * sc;
        float4 v = x[idx];
        v.x = fmaxf(v.x * sc + sh, 0.f);
        v.y = fmaxf(v.y * sc + sh, 0.f);
        v.z = fmaxf(v.z * sc + sh, 0.f);
        v.w = fmaxf(v.w * sc + sh, 0.f);
        if (res) {
            float4 r = res[idx];
            v.x += r.x; v.y += r.y; v.z += r.z; v.w += r.w;
        }
        x[idx] = v;
        if (ahi) {
            __nv_bfloat16 hx = __float2bfloat16_rn(v.x);
            __nv_bfloat16 hy = __float2bfloat16_rn(v.y);
            __nv_bfloat16 hz = __float2bfloat16_rn(v.z);
            __nv_bfloat16 hw = __float2bfloat16_rn(v.w);
            ahi[2 * idx]     = __nv_bfloat162{hx, hy};
            ahi[2 * idx + 1] = __nv_bfloat162{hz, hw};
            alo[2 * idx] = __nv_bfloat162{
                __float2bfloat16_rn(v.x - __bfloat162float(hx)),
                __float2bfloat16_rn(v.y - __bfloat162float(hy))};
            alo[2 * idx + 1] = __nv_bfloat162{
                __float2bfloat16_rn(v.z - __bfloat162float(hz)),
                __float2bfloat16_rn(v.w - __bfloat162float(hw))};
        }
    }
}

// ---------------- conv2 (f32x2), fused: BN1-apply + writeback, stats, tail-block CSR fill ----------------
__global__ __launch_bounds__(256) void conv2_kernel(
    float* __restrict__ io_cnn1, const float* __restrict__ w,
    const float* __restrict__ bias,
    const float* __restrict__ g1, const float* __restrict__ b1,
    float* __restrict__ out, const int* __restrict__ edges)
{
    __shared__ float sx[32 * L_LEN + 64];
    __shared__ float swT[64 * 64];
    __shared__ float sb[64], ssc[64], ssh[64];
    int n = blockIdx.x, t = threadIdx.x;
    if (n >= N_NODES) {
        int e = (n - N_NODES) * 256 + t;
        if (e < N_EDGES) {
            int sN = edges[2 * e], d = edges[2 * e + 1];
            int idx = atomicAdd(&g_pos[d], 1);
            g_csr[idx] = sN;
        }
        return;
    }
    for (int i = t; i < 64 * 64; i += 256) {
        int o = i >> 6, c = i & 63;
        swT[c * 64 + o] = w[i];
    }
    if (t < 64) {
        sb[t] = bias[t];
        sx[32 * L_LEN + t] = 0.f;
        const float invc = 1.0f / ((float)N_NODES * L_LEN);
        float m   = g_sum[t] * invc;
        float var = g_sq[t] * invc - m * m;
        float sc  = rsqrtf(var + EPS) * g1[t];
        ssc[t] = sc;
        ssh[t] = b1[t] - m * sc;
    }
    int tx = t & 15, ty = t >> 4;
    unsigned int sx_base = smem_u32(sx) + tx * 16;

    ull acc[3][4][2];
#pragma unroll
    for (int a = 0; a < 3; a++)
#pragma unroll
        for (int j = 0; j < 4; j++) { acc[a][j][0] = 0ull; acc[a][j][1] = 0ull; }

    for (int cp = 0; cp < 2; cp++) {
        __syncthreads();
        for (int i = t; i < 32 * L_LEN; i += 256) {
            int ch = cp * 32 + i / L_LEN;
            size_t gidx = (size_t)n * IN_FEATS + cp * 32 * L_LEN + i;
            float raw = io_cnn1[gidx];
            float v = fmaxf(raw * ssc[ch] + ssh[ch], 0.f);
            sx[i] = v;
            io_cnn1[gidx] = v;      // post-BN cnn1 output
        }
        __syncthreads();
#pragma unroll 4
        for (int cc = 0; cc < 32; cc++) {
            float wv[4];
            *(float4*)wv = *(const float4*)&swT[(cp * 32 + cc) * 64 + ty * 4];
            ull w2[4];
#pragma unroll
            for (int j = 0; j < 4; j++) w2[j] = pkdup(wv[j]);
#pragma unroll
            for (int lp = 0; lp < 3; lp++) {
                ull x0, x1;
                lds2w(x0, x1, sx_base + cc * (L_LEN * 4) + lp * 256);
#pragma unroll
                for (int j = 0; j < 4; j++) {
                    ffma2(acc[lp][j][0], w2[j], x0);
                    ffma2(acc[lp][j][1], w2[j], x1);
                }
            }
        }
    }
    // store + per-channel stats partials (conflict-free shfl reduce)
    float ts[4] = {0.f, 0.f, 0.f, 0.f}, tq[4] = {0.f, 0.f, 0.f, 0.f};
#pragma unroll
    for (int lp = 0; lp < 3; lp++) {
        int l0 = lp * 64 + tx * 4;
        if (l0 >= L_LEN) continue;     // only lp==2, tx>=3
#pragma unroll
        for (int j = 0; j < 4; j++) {
            int o = ty * 4 + j;
            float4 v;
            unpk(acc[lp][j][0], v.x, v.y);
            unpk(acc[lp][j][1], v.z, v.w);
            v.x += sb[o]; v.y += sb[o]; v.z += sb[o]; v.w += sb[o];
            *(float4*)&out[(size_t)n * IN_FEATS + o * L_LEN + l0] = v;
            ts[j] += v.x + v.y + v.z + v.w;
            tq[j] += v.x * v.x + v.y * v.y + v.z * v.z + v.w * v.w;
        }
    }
#pragma unroll
    for (int j = 0; j < 4; j++) {
#pragma unroll
        for (int o = 8; o > 0; o >>= 1) {
            ts[j] += __shfl_xor_sync(0xffffffffu, ts[j], o);
            tq[j] += __shfl_xor_sync(0xffffffffu, tq[j], o);
        }
    }
    if (tx == 0) {
#pragma unroll
        for (int j = 0; j < 4; j++) {
            atomicAdd(&g_sum[64 + ty * 4 + j], ts[j]);
            atomicAdd(&g_sq [64 + ty * 4 + j], tq[j]);
        }
    }
}

// ---------------- degree prefix scan ----------------
__global__ __launch_bounds__(1024) void scan_kernel() {
    __shared__ int s[1024];
    const int CHUNK = 10;
    int t = threadIdx.x;
    int base = t * CHUNK;
    int loc[CHUNK];
    int sum = 0;
#pragma unroll
    for (int i = 0; i < CHUNK; i++) {
        int v = (base + i < N_NODES) ? g_deg[base + i] : 0;
        loc[i] = sum; sum += v;
    }
    s[t] = sum;
    __syncthreads();
    for (int d = 1; d < 1024; d <<= 1) {
        int v = (t >= d) ? s[t - d] : 0;
        __syncthreads();
        s[t] += v;
        __syncthreads();
    }
    int prev = t ? s[t - 1] : 0;
#pragma unroll
    for (int i = 0; i < CHUNK; i++) {
        int n = base + i;
        if (n < N_NODES) {
            int o = prev + loc[i];
            g_off[n] = o; g_pos[n] = o;
            g_denom[n] = (float)max(g_deg[n], 1);
        }
    }
    if (t == 1023) g_off[N_NODES] = s[1023];
}

// ---------------- weight transpose + bf16 split: W[K][256]x2 -> Wcat^T[512][K] ----------------
__global__ void wsplit_kernel(const float* __restrict__ ws, const float* __restrict__ wn,
                              __nv_bfloat16* __restrict__ whi,
                              __nv_bfloat16* __restrict__ wlo, int K)
{
    __shared__ float tile[32][33];
    int k0 = blockIdx.x * 32, n0 = blockIdx.y * 32;
    int tx = threadIdx.x, ty = threadIdx.y;   // 32 x 8
#pragma unroll
    for (int r = 0; r < 32; r += 8) {
        int k = k0 + ty + r, n = n0 + tx;
        float v = (n < 256) ? ws[(size_t)k * 256 + n] : wn[(size_t)k * 256 + n - 256];
        tile[ty + r][tx] = v;
    }
    __syncthreads();
#pragma unroll
    for (int r = 0; r < 32; r += 8) {
        int n = n0 + ty + r, k = k0 + tx;
        float v = tile[tx][ty + r];
        __nv_bfloat16 h = __float2bfloat16_rn(v);
        whi[(size_t)n * K + k] = h;
        wlo[(size_t)n * K + k] = __float2bfloat16_rn(v - __bfloat162float(h));
    }
}

// ---------------- HMMA bf16 split GEMM, A-reuse fused, M-tile 96 / 192 threads ----------------
#define MT 96
#define GSTAGE 22528
#define GEMM_SMEM_F (3 * GSTAGE)

__device__ __forceinline__ unsigned int swz(unsigned int base, int row, int kc) {
    return base + row * 64 + ((kc ^ ((row >> 1) & 3)) << 4);
}

__device__ __forceinline__ void fused_issue_load(
    const __nv_bfloat16* __restrict__ Ap,
    const __nv_bfloat16* __restrict__ B0p,
    const __nv_bfloat16* __restrict__ B1p,
    unsigned int sa, unsigned int sb0, unsigned int sb1,
    int m0, int n0, int k0, int K, int tid, bool dual)
{
#pragma unroll
    for (int i = 0; i < 2; i++) {
        int idx = tid + i * 192;
        int row = idx >> 2, cch = idx & 3;
        int rg = m0 + row; if (rg > N_NODES - 1) rg = N_NODES - 1;
        CP16(swz(sa, row, cch), Ap + (size_t)rg * K + k0 + cch * 8);
    }
#pragma unroll
    for (int i = 0; i < 3; i++) {
        int idx = tid + i * 192;
        if (idx < 512) {
            int row = idx >> 2, cch = idx & 3;
            CP16(swz(sb0, row, cch), B0p + (size_t)(n0 + row) * K + k0 + cch * 8);
        }
    }
    if (dual) {
#pragma unroll
        for (int i = 0; i < 3; i++) {
            int idx = tid + i * 192;
            if (idx < 512) {
                int row = idx >> 2, cch = idx & 3;
                CP16(swz(sb1, row, cch), B1p + (size_t)(n0 + row) * K + k0 + cch * 8);
            }
        }
    }
    asm volatile("cp.async.commit_group;");
}

__global__ __launch_bounds__(192, 3) void gemm_mma_kernel(
    const __nv_bfloat16* __restrict__ Ahi, const __nv_bfloat16* __restrict__ Alo,
    const __nv_bfloat16* __restrict__ Bhi, const __nv_bfloat16* __restrict__ Blo,
    float* __restrict__ Cs, float* __restrict__ Cn, int K)
{
    extern __shared__ __align__(1024) char gsm[];
    unsigned int base0 = smem_u32(gsm);
    int tid = threadIdx.x, wid = tid >> 5, lane = tid & 31;
    int m0 = blockIdx.y * MT;
    int n0 = blockIdx.x * 128;         // 0..384 within [ws|wn]
    int wm = (wid % 3) * 32;
    int wn = (wid / 3) * 64;

    unsigned int sa[3], sb0[3], sb1[3];
#pragma unroll
    for (int s = 0; s < 3; s++) {
        sa[s]  = base0 + s * GSTAGE;
        sb0[s] = sa[s] + 6144;
        sb1[s] = sb0[s] + 8192;
    }

    const int KC = K / 32, NCH = 2 * KC;   // KC >= 8 always

    float acc[2][8][4];
#pragma unroll
    for (int i = 0; i < 2; i++)
#pragma unroll
        for (int j = 0; j < 8; j++)
#pragma unroll
            for (int q = 0; q < 4; q++) acc[i][j][q] = 0.f;

    fused_issue_load(Ahi, Bhi, Blo, sa[0], sb0[0], sb1[0], m0, n0, 0,  K, tid, true);
    fused_issue_load(Ahi, Bhi, Blo, sa[1], sb0[1], sb1[1], m0, n0, 32, K, tid, true);

    for (int c = 0; c < NCH; c++) {
        if (c < NCH - 1) asm volatile("cp.async.wait_group 1;");
        else             asm volatile("cp.async.wait_group 0;");
        __syncthreads();
        if (c + 2 < NCH) {
            int cf = c + 2;
            bool p1f = cf < KC;
            int k0f = (p1f ? cf : cf - KC) * 32;
            int sf = cf % 3;
            fused_issue_load(p1f ? Ahi : Alo, Bhi, Blo,
                             sa[sf], sb0[sf], sb1[sf], m0, n0, k0f, K, tid, p1f);
        }
        int s = c % 3;
        bool p1 = c < KC;
        unsigned int sas = sa[s], sb0s = sb0[s], sb1s = sb1[s];
#pragma unroll
        for (int ks = 0; ks < 2; ks++) {
            int kc = ks * 2 + (lane >> 4);
            unsigned int a[2][4], b[4][4];
            LDSM4(a[0], swz(sas, wm + (lane & 15), kc));
            LDSM4(a[1], swz(sas, wm + 16 + (lane & 15), kc));
#pragma unroll
            for (int j = 0; j < 4; j++)
                LDSM4(b[j], swz(sb0s, wn + j * 16 + (lane & 15), kc));
#pragma unroll
            for (int mi = 0; mi < 2; mi++)
#pragma unroll
                for (int j = 0; j < 4; j++) {
                    MMA16816(acc[mi][2 * j],     a[mi], b[j][0], b[j][2]);
                    MMA16816(acc[mi][2 * j + 1], a[mi], b[j][1], b[j][3]);
                }
            if (p1) {
#pragma unroll
                for (int j = 0; j < 4; j++)
                    LDSM4(b[j], swz(sb1s, wn + j * 16 + (lane & 15), kc));
#pragma unroll
                for (int mi = 0; mi < 2; mi++)
#pragma unroll
                    for (int j = 0; j < 4; j++) {
                        MMA16816(acc[mi][2 * j],     a[mi], b[j][0], b[j][2]);
                        MMA16816(acc[mi][2 * j + 1], a[mi], b[j][1], b[j][3]);
                    }
            }
        }
    }

    // epilogue
    float* Cout = (n0 < 256) ? Cs : Cn;
    int ncol0 = n0 & 255;
    int g = lane >> 2, tq = lane & 3;
#pragma unroll
    for (int mi = 0; mi < 2; mi++) {
        int r0 = m0 + wm + mi * 16 + g;
#pragma unroll
        for (int j = 0; j < 8; j++) {
            int col = ncol0 + wn + j * 8 + tq * 2;
            if (r0 < N_NODES)
                *(float2*)&Cout[(size_t)r0 * 256 + col] =
                    make_float2(acc[mi][j][0], acc[mi][j][1]);
            if (r0 + 8 < N_NODES)
                *(float2*)&Cout[(size_t)(r0 + 8) * 256 + col] =
                    make_float2(acc[mi][j][2], acc[mi][j][3]);
        }
    }
}

// ---------------- fp32 SIMT GEMM (MLP head only) ----------------
__global__ __launch_bounds__(256, 2) void gemm2_kernel(
    const float* __restrict__ A,
    const float* __restrict__ B0, const float* __restrict__ B1,
    float* __restrict__ C0, float* __restrict__ C1,
    int M, int Nc, int K, int nxHalf)
{
    __shared__ float As[8][264];
    __shared__ float Bs[8][132];
    int bx = blockIdx.x;
    const float* B = B0;
    float* C = C0;
    if (bx >= nxHalf) { B = B1; C = C1; bx -= nxHalf; }
    int tid = threadIdx.x;
    int m0 = blockIdx.y * 128, n0 = bx * 128;
    int tx = tid & 15, ty = tid >> 4;

    ull acc[8][4];
#pragma unroll
    for (int i = 0; i < 8; i++)
#pragma unroll
        for (int j = 0; j < 4; j++) acc[i][j] = 0ull;

    int a_row = tid >> 1, a_col = (tid & 1) * 4;
    int b_row = tid >> 5, b_col = (tid & 31) * 4;
    bool a_ok = (m0 + a_row) < M;
    bool b_ok = (n0 + b_col) < Nc;
    const float* Abase = A + (size_t)(m0 + a_row) * K + a_col;
    const float* Bbase = B + n0 + b_col;

    unsigned int as0 = smem_u32(As);
    unsigned int bs0 = smem_u32(Bs);
    unsigned int as_w = as0 + a_col * (264 * 4) + a_row * 8;
    unsigned int as_r = as0 + ty * 32;
    unsigned int bs_r = bs0 + tx * 16;

    for (int k0 = 0; k0 < K; k0 += 8) {
        float4 av = a_ok ? *(const float4*)(Abase + k0) : make_float4(0, 0, 0, 0);
        float4 bv = b_ok ? *(const float4*)(Bbase + (size_t)(k0 + b_row) * Nc)
                         : make_float4(0, 0, 0, 0);
        __syncthreads();
        sts64(as_w + 0 * 1056, pkdup(av.x));
        sts64(as_w + 1 * 1056, pkdup(av.y));
        sts64(as_w + 2 * 1056, pkdup(av.z));
        sts64(as_w + 3 * 1056, pkdup(av.w));
        *(float4*)&Bs[b_row][b_col] = bv;
        __syncthreads();
#pragma unroll
        for (int kk = 0; kk < 8; kk++) {
            ull a2[8], b2[4];
            unsigned int ar = as_r + kk * 1056;
            unsigned int br = bs_r + kk * 528;
            lds2w(a2[0], a2[1], ar);
            lds2w(a2[2], a2[3], ar + 16);
            lds2w(a2[4], a2[5], ar + 512);
            lds2w(a2[6], a2[7], ar + 528);
            lds2w(b2[0], b2[1], br);
            lds2w(b2[2], b2[3], br + 256);
#pragma unroll
            for (int i = 0; i < 8; i++)
#pragma unroll
                for (int j = 0; j < 4; j++) ffma2(acc[i][j], a2[i], b2[j]);
        }
    }
#pragma unroll
    for (int bi = 0; bi < 2; bi++)
#pragma unroll
        for (int i = 0; i < 4; i++) {
            int r = m0 + bi * 64 + ty * 4 + i;
            if (r >= M) continue;
            int i8 = bi * 4 + i;
#pragma unroll
            for (int bj = 0; bj < 2; bj++) {
                int c = n0 + bj * 64 + tx * 4;
                if (c >= Nc) continue;
                float4 v;
                unpk(acc[i8][2 * bj + 0], v.x, v.y);
                unpk(acc[i8][2 * bj + 1], v.z, v.w);
                *(float4*)&C[(size_t)r * Nc + c] = v;
            }
        }
}

// ---------------- neighbor gather (CSR) + combine ----------------
__global__ __launch_bounds__(256) void neigh_combine_kernel(
    const float* __restrict__ hn, const float* __restrict__ hs,
    const float* __restrict__ bias, float* __restrict__ h2)
{
    int n = blockIdx.x, t = threadIdx.x;
    __shared__ int sidx[256];
    int s0 = g_off[n], s1 = g_off[n + 1];
    float acc = 0.f;
    for (int base = s0; base < s1; base += 256) {
        int cnt = min(256, s1 - base);
        __syncthreads();
        if (t < cnt) sidx[t] = g_csr[base + t];
        __syncthreads();
        for (int j = 0; j < cnt; j++) acc += hn[(size_t)sidx[j] * HID + t];
    }
    h2[(size_t)n * HID + t] = hs[(size_t)n * HID + t] + acc / g_denom[n] + bias[t];
}

// ---------------- per-column stats ----------------
__global__ void col_stats_kernel(const float* __restrict__ x, int rows) {
    int c = threadIdx.x, cols = blockDim.x;
    float s = 0.f, q = 0.f;
    for (int r = blockIdx.x; r < rows; r += gridDim.x) {
        float v = x[(size_t)r * cols + c];
        s += v; q += v * v;
    }
    atomicAdd(&g_sum[c], s);
    atomicAdd(&g_sq[c],  q);
}

// ---------------- node BN + residual + relu (float4); optional bf16 split out ----------------
__global__ void bn_apply_kernel(
    const float4* __restrict__ x, const float4* __restrict__ pre,
    float4* __restrict__ outp, float4* __restrict__ aux,
    const float* __restrict__ gam, const float* __restrict__ bet,
    __nv_bfloat162* __restrict__ ahi, __nv_bfloat162* __restrict__ alo)
{
    const float invn = 1.0f / (float)N_NODES;
    const int total4 = N_NODES * (HID / 4);
    for (int idx = blockIdx.x * blockDim.x + threadIdx.x; idx < total4;
         idx += gridDim.x * blockDim.x) {
        int c0 = (idx & (HID / 4 - 1)) * 4;
        float sc[4], sh[4];
#pragma unroll
        for (int i = 0; i < 4; i++) {
            float m   = g_sum[c0 + i] * invn;
            float var = g_sq[c0 + i] * invn - m * m;
            sc[i] = rsqrtf(var + EPS) * gam[c0 + i];
            sh[i] = bet[c0 + i] - m * sc[i];
        }
        float4 v = x[idx];
        v.x = v.x * sc[0] + sh[0];
        v.y = v.y * sc[1] + sh[1];
        v.z = v.z * sc[2] + sh[2];
        v.w = v.w * sc[3] + sh[3];
        if (pre) {
            float4 p = pre[idx];
            v.x += p.x; v.y += p.y; v.z += p.z; v.w += p.w;
        }
        v.x = fmaxf(v.x, 0.f);
        v.y = fmaxf(v.y, 0.f);
        v.z = fmaxf(v.z, 0.f);
        v.w = fmaxf(v.w, 0.f);
        outp[idx] = v;
        if (aux) aux[idx] = v;
        if (ahi) {
            __nv_bfloat16 hx = __float2bfloat16_rn(v.x);
            __nv_bfloat16 hy = __float2bfloat16_rn(v.y);
            __nv_bfloat16 hz = __float2bfloat16_rn(v.z);
            __nv_bfloat16 hw = __float2bfloat16_rn(v.w);
            ahi[2 * idx]     = __nv_bfloat162{hx, hy};
            ahi[2 * idx + 1] = __nv_bfloat162{hz, hw};
            alo[2 * idx] = __nv_bfloat162{
                __float2bfloat16_rn(v.x - __bfloat162float(hx)),
                __float2bfloat16_rn(v.y - __bfloat162float(hy))};
            alo[2 * idx + 1] = __nv_bfloat162{
                __float2bfloat16_rn(v.z - __bfloat162float(hz)),
                __float2bfloat16_rn(v.w - __bfloat162float(hw))};
        }
    }
}

// ---------------- MLP head ----------------
__global__ __launch_bounds__(128) void mlp_out_kernel(
    const float* __restrict__ z, const float* __restrict__ gam,
    const float* __restrict__ bet, const float* __restrict__ w2,
    const float* __restrict__ b2, float* __restrict__ out)
{
    __shared__ float sm[64], si[64], sg[64], sb[64], sw[128], sb2[2];
    int t = threadIdx.x;
    if (t < 64) {
        float m   = g_sum[t] / (float)N_NODES;
        float var = g_sq[t] / (float)N_NODES - m * m;
        sm[t] = m;
        si[t] = rsqrtf(var + EPS);
        sg[t] = gam[t];
        sb[t] = bet[t];
    }
    if (t < 128) sw[t] = w2[t];
    if (t < 2)   sb2[t] = b2[t];
    __syncthreads();
    int n = blockIdx.x * 128 + t;
    if (n < N_NODES) {
        float a0 = sb2[0], a1 = sb2[1];
        const float* zr = z + (size_t)n * 64;
#pragma unroll
        for (int j = 0; j < 64; j++) {
            float v = (zr[j] - sm[j]) * si[j] * sg[j] + sb[j];
            v = fmaxf(v, 0.f);
            a0 += v * sw[2 * j];
            a1 += v * sw[2 * j + 1];
        }
        out[2 * n]     = a0;
        out[2 * n + 1] = a1;
    }
}

// ---------------- host ----------------
extern "C" void kernel_launch(void* const* d_in, const int* in_sizes, int n_in,
                              void* d_out, int out_size)
{
    const float* inputs  = (const float*)d_in[0];
    const float* conv1_w = (const float*)d_in[1];
    const float* conv1_b = (const float*)d_in[2];
    const float* bn_c1_g = (const float*)d_in[3];
    const float* bn_c1_b = (const float*)d_in[4];
    const float* conv2_w = (const float*)d_in[5];
    const float* conv2_b = (const float*)d_in[6];
    const float* bn_c2_g = (const float*)d_in[7];
    const float* bn_c2_b = (const float*)d_in[8];
    const float* ws0     = (const float*)d_in[9];
    const float* wn0     = (const float*)d_in[10];
    const float* b0      = (const float*)d_in[11];
    const float* ws_rest = (const float*)d_in[12];
    const float* wn_rest = (const float*)d_in[13];
    const float* b_rest  = (const float*)d_in[14];
    const float* bn_g    = (const float*)d_in[15];
    const float* bn_b    = (const float*)d_in[16];
    const float* mlp_w1  = (const float*)d_in[17];
    // d_in[18] = mlp_b1 : constant shift, cancels exactly inside batchnorm
    const float* mlp_bn_g = (const float*)d_in[19];
    const float* mlp_bn_b = (const float*)d_in[20];
    const float* mlp_w2   = (const float*)d_in[21];
    const float* mlp_b2   = (const float*)d_in[22];
    const int*   edges    = (const int*)d_in[23];

    float* out  = (float*)d_out;
    float* cnn1 = out + CNN1_OFF;
    float* cnn2 = out + CNN2_OFF;
    float* fin  = out + FIN_OFF;

    float *hb, *h2b, *hnb, *hsb, *zb;
    __nv_bfloat16 *ahib, *alob, *whib, *wlob;
    cudaGetSymbolAddress((void**)&hb,   g_h);
    cudaGetSymbolAddress((void**)&h2b,  g_h2);
    cudaGetSymbolAddress((void**)&hnb,  g_hn);
    cudaGetSymbolAddress((void**)&hsb,  g_hs);
    cudaGetSymbolAddress((void**)&zb,   g_z);
    cudaGetSymbolAddress((void**)&ahib, g_Ahi);
    cudaGetSymbolAddress((void**)&alob, g_Alo);
    cudaGetSymbolAddress((void**)&whib, g_Whi);
    cudaGetSymbolAddress((void**)&wlob, g_Wlo);

    cudaFuncSetAttribute(gemm_mma_kernel,
                         cudaFuncAttributeMaxDynamicSharedMemorySize, GEMM_SMEM_F);

    // ---- weight transpose + split ----
    wsplit_kernel<<<dim3(IN_FEATS / 32, 16), dim3(32, 8)>>>(ws0, wn0, whib, wlob, IN_FEATS);
    for (int l = 1; l < 4; l++) {
        wsplit_kernel<<<dim3(HID / 32, 16), dim3(32, 8)>>>(
            ws_rest + (size_t)(l - 1) * HID * HID,
            wn_rest + (size_t)(l - 1) * HID * HID,
            whib + W_L0_ELEMS + (size_t)(l - 1) * W_REST_ELEMS,
            wlob + W_L0_ELEMS + (size_t)(l - 1) * W_REST_ELEMS, HID);
    }

    // ---- CNN front-end (+ CSR build riding in tail blocks) ----
    zero_stats_kernel<<<1, 256>>>();
    zero_deg_kernel<<<(N_NODES + 255) / 256, 256>>>();
    conv1_kernel<<<N_NODES + EDGE_BLOCKS, 256>>>(inputs, conv1_w, conv1_b, cnn1, edges);
    scan_kernel<<<1, 1024>>>();
    conv2_kernel<<<N_NODES + EDGE_BLOCKS, 256>>>(cnn1, conv2_w, conv2_b,
                                                 bn_c1_g, bn_c1_b, cnn2, edges);
    bn_chan_apply_kernel<<<8192, 256>>>((float4*)cnn2, (const float4*)cnn1,
                                        bn_c2_g, bn_c2_b,
                                        (__nv_bfloat162*)ahib, (__nv_bfloat162*)alob, 64);

    // ---- 4 GraphSAGE layers (HMMA split-bf16 GEMMs, A-reuse fused, M96 tiles) ----
    for (int l = 0; l < 4; l++) {
        int K = (l == 0) ? IN_FEATS : HID;
        const __nv_bfloat16* wh =
            whib + ((l == 0) ? 0 : W_L0_ELEMS + (size_t)(l - 1) * W_REST_ELEMS);
        const __nv_bfloat16* wl =
            wlob + ((l == 0) ? 0 : W_L0_ELEMS + (size_t)(l - 1) * W_REST_ELEMS);
        const float* bb = (l == 0) ? b0 : b_rest + (size_t)(l - 1) * HID;

        gemm_mma_kernel<<<dim3(4, (N_NODES + MT - 1) / MT), 192, GEMM_SMEM_F>>>(
            ahib, alob, wh, wl, hsb, hnb, K);

        neigh_combine_kernel<<<N_NODES, 256>>>(hnb, hsb, bb, h2b);

        zero_stats_kernel<<<1, 256>>>();
        col_stats_kernel<<<512, HID>>>(h2b, N_NODES);
        bn_apply_kernel<<<2560, 256>>>(
            (const float4*)h2b, (l > 0) ? (const float4*)hb : nullptr,
            (float4*)hb, (l == 3) ? (float4*)fin : nullptr,
            bn_g + (size_t)l * HID, bn_b + (size_t)l * HID,
            (l < 3) ? (__nv_bfloat162*)ahib : nullptr,
            (l < 3) ? (__nv_bfloat162*)alob : nullptr);
    }

    // ---- MLP head ----
    {
        dim3 grid(1, 79);
        gemm2_kernel<<<grid, 256>>>(hb, mlp_w1, mlp_w1, zb, zb, N_NODES, C_MID, HID, 1);
        zero_stats_kernel<<<1, 256>>>();
        col_stats_kernel<<<2048, C_MID>>>(zb, N_NODES);
        mlp_out_kernel<<<(N_NODES + 127) / 128, 128>>>(
            zb, mlp_bn_g, mlp_bn_b, mlp_w2, mlp_b2, out);
    }
}

// round 17
// speedup vs baseline: 1.0479x; 1.0479x over previous
#include <cuda_runtime.h>
#include <cuda_bf16.h>

#define N_NODES 10000
#define N_EDGES 320000
#define HID 256
#define L_LEN 140
#define C_IN 5
#define C_MID 64
#define IN_FEATS (C_MID * L_LEN)   // 8960
#define EPS 1e-5f

// d_out layout: [out (N*2)][cnn1 (N*64*140)][cnn2 (N*64*140)][fin (N*256)]
#define CNN1_OFF (N_NODES * 2)
#define CNN2_OFF (CNN1_OFF + N_NODES * C_MID * L_LEN)
#define FIN_OFF  (CNN2_OFF + N_NODES * C_MID * L_LEN)

// weight (transposed, split) buffer: layer0 512x8960, layers1-3 512x256
#define W_L0_ELEMS (512 * IN_FEATS)
#define W_REST_ELEMS (512 * HID)
#define W_TOTAL (W_L0_ELEMS + 3 * W_REST_ELEMS)

typedef unsigned long long ull;

// ---------------- f32x2 helpers ----------------
__device__ __forceinline__ ull pkdup(float x) {
    unsigned int u = __float_as_uint(x);
    ull r;
    asm("mov.b64 %0, {%1, %1};" : "=l"(r) : "r"(u));
    return r;
}
__device__ __forceinline__ void ffma2(ull& d, ull a, ull b) {
    asm("fma.rn.f32x2 %0, %1, %2, %0;" : "+l"(d) : "l"(a), "l"(b));
}
__device__ __forceinline__ void unpk(ull v, float& lo, float& hi) {
    unsigned int a, b;
    asm("mov.b64 {%0, %1}, %2;" : "=r"(a), "=r"(b) : "l"(v));
    lo = __uint_as_float(a);
    hi = __uint_as_float(b);
}
__device__ __forceinline__ void lds2w(ull& p0, ull& p1, unsigned int addr) {
    asm volatile("ld.shared.v2.b64 {%0, %1}, [%2];" : "=l"(p0), "=l"(p1) : "r"(addr));
}
__device__ __forceinline__ void sts64(unsigned int addr, ull v) {
    asm volatile("st.shared.b64 [%0], %1;" :: "r"(addr), "l"(v));
}
__device__ __forceinline__ unsigned int smem_u32(const void* p) {
    unsigned int a;
    asm("{ .reg .u64 t; cvta.to.shared.u64 t, %1; cvt.u32.u64 %0, t; }" : "=r"(a) : "l"(p));
    return a;
}

// ---------------- mma.sync / ldmatrix / cp.async helpers ----------------
#define LDSM4(r, addr) \
    asm volatile("ldmatrix.sync.aligned.m8n8.x4.shared.b16 {%0,%1,%2,%3}, [%4];" \
                 : "=r"((r)[0]), "=r"((r)[1]), "=r"((r)[2]), "=r"((r)[3]) : "r"(addr))

#define MMA16816(d, a, b0, b1) \
    asm volatile("mma.sync.aligned.m16n8k16.row.col.f32.bf16.bf16.f32 " \
                 "{%0,%1,%2,%3}, {%4,%5,%6,%7}, {%8,%9}, {%0,%1,%2,%3};" \
                 : "+f"((d)[0]), "+f"((d)[1]), "+f"((d)[2]), "+f"((d)[3]) \
                 : "r"((a)[0]), "r"((a)[1]), "r"((a)[2]), "r"((a)[3]), \
                   "r"(b0), "r"(b1))

#define CP16(daddr, gptr) \
    asm volatile("cp.async.cg.shared.global [%0], [%1], 16;" \
                 :: "r"(daddr), "l"(gptr))

// ---------------- scratch (static device memory; no allocs) ----------------
__device__ float g_h [N_NODES * HID];
__device__ float g_h2[N_NODES * HID];
__device__ float g_hn[N_NODES * HID];
__device__ float g_hs[N_NODES * HID];
__device__ float g_z [N_NODES * C_MID];
__device__ float g_sum[HID];
__device__ float g_sq [HID];
__device__ float g_denom[N_NODES];
__device__ int   g_deg[N_NODES];
__device__ int   g_off[N_NODES + 1];
__device__ int   g_pos[N_NODES];
__device__ int   g_csr[N_EDGES];
__device__ __nv_bfloat16 g_Ahi[N_NODES * IN_FEATS];
__device__ __nv_bfloat16 g_Alo[N_NODES * IN_FEATS];
__device__ __nv_bfloat16 g_Whi[W_TOTAL];
__device__ __nv_bfloat16 g_Wlo[W_TOTAL];

// ---------------- small utility kernels ----------------
__global__ void zero_stats_kernel() {
    int t = threadIdx.x;
    g_sum[t] = 0.f;
    g_sq[t]  = 0.f;
}
__global__ void zero_deg_kernel() {
    int i = blockIdx.x * blockDim.x + threadIdx.x;
    if (i < N_NODES) g_deg[i] = 0;
}

// ---------------- conv1 + fused per-channel stats (warp-per-channel, conflict-free) ----------------
__global__ __launch_bounds__(256) void conv1_kernel(
    const float* __restrict__ x, const float* __restrict__ w,
    const float* __restrict__ bias, float* __restrict__ out)
{
    __shared__ float sx[C_IN * L_LEN];
    __shared__ float sw[C_MID * C_IN];
    __shared__ float sb[C_MID];
    int n = blockIdx.x, t = threadIdx.x;
    int warp = t >> 5, lane = t & 31;
    for (int i = t; i < C_IN * L_LEN; i += 256) sx[i] = x[(size_t)n * C_IN * L_LEN + i];
    for (int i = t; i < C_MID * C_IN; i += 256) sw[i] = w[i];
    if (t < C_MID) sb[t] = bias[t];
    __syncthreads();
#pragma unroll
    for (int j = 0; j < 8; j++) {
        int o = warp * 8 + j;
        float w0 = sw[o * C_IN + 0], w1 = sw[o * C_IN + 1], w2 = sw[o * C_IN + 2];
        float w3 = sw[o * C_IN + 3], w4 = sw[o * C_IN + 4];
        float bb = sb[o];
        float s = 0.f, q = 0.f;
#pragma unroll
        for (int i = 0; i < 5; i++) {
            int l = lane + 32 * i;
            if (l < L_LEN) {
                float val = bb + w0 * sx[l] + w1 * sx[L_LEN + l] + w2 * sx[2 * L_LEN + l]
                               + w3 * sx[3 * L_LEN + l] + w4 * sx[4 * L_LEN + l];
                out[(size_t)n * IN_FEATS + o * L_LEN + l] = val;
                s += val;
                q += val * val;
            }
        }
#pragma unroll
        for (int off = 16; off > 0; off >>= 1) {
            s += __shfl_down_sync(0xffffffffu, s, off);
            q += __shfl_down_sync(0xffffffffu, q, off);
        }
        if (lane == 0) {
            atomicAdd(&g_sum[o], s);
            atomicAdd(&g_sq[o],  q);
        }
    }
}

// ---------------- channel BN + relu (+residual) in-place; optional bf16 hi/lo split out ----------------
__global__ void bn_chan_apply_kernel(
    float4* __restrict__ x, const float4* __restrict__ res,
    const float* __restrict__ gam, const float* __restrict__ bet,
    __nv_bfloat162* __restrict__ ahi, __nv_bfloat162* __restrict__ alo, int soff)
{
    const float invc = 1.0f / ((float)N_NODES * L_LEN);
    const int total4 = N_NODES * C_MID * (L_LEN / 4);
    for (int idx = blockIdx.x * blockDim.x + threadIdx.x; idx < total4;
         idx += gridDim.x * blockDim.x) {
        int ch = (idx / (L_LEN / 4)) & (C_MID - 1);
        float m   = g_sum[soff + ch] * invc;
        float var = g_sq[soff + ch] * invc - m * m;
        float sc  = rsqrtf(var + EPS) * gam[ch];
        float sh  = bet[ch] - m * sc;
        float4 v = x[idx];
        v.x = fmaxf(v.x * sc + sh, 0.f);
        v.y = fmaxf(v.y * sc + sh, 0.f);
        v.z = fmaxf(v.z * sc + sh, 0.f);
        v.w = fmaxf(v.w * sc + sh, 0.f);
        if (res) {
            float4 r = res[idx];
            v.x += r.x; v.y += r.y; v.z += r.z; v.w += r.w;
        }
        x[idx] = v;
        if (ahi) {
            __nv_bfloat16 hx = __float2bfloat16_rn(v.x);
            __nv_bfloat16 hy = __float2bfloat16_rn(v.y);
            __nv_bfloat16 hz = __float2bfloat16_rn(v.z);
            __nv_bfloat16 hw = __float2bfloat16_rn(v.w);
            ahi[2 * idx]     = __nv_bfloat162{hx, hy};
            ahi[2 * idx + 1] = __nv_bfloat162{hz, hw};
            alo[2 * idx] = __nv_bfloat162{
                __float2bfloat16_rn(v.x - __bfloat162float(hx)),
                __float2bfloat16_rn(v.y - __bfloat162float(hy))};
            alo[2 * idx + 1] = __nv_bfloat162{
                __float2bfloat16_rn(v.z - __bfloat162float(hz)),
                __float2bfloat16_rn(v.w - __bfloat162float(hw))};
        }
    }
}

// ---------------- conv2 (f32x2), fused: BN1-apply on load + writeback, stats on store ----------------
__global__ __launch_bounds__(256) void conv2_kernel(
    float* __restrict__ io_cnn1, const float* __restrict__ w,
    const float* __restrict__ bias,
    const float* __restrict__ g1, const float* __restrict__ b1,
    float* __restrict__ out)
{
    __shared__ float sx[32 * L_LEN + 64];
    __shared__ float swT[64 * 64];
    __shared__ float sb[64], ssc[64], ssh[64];
    int n = blockIdx.x, t = threadIdx.x;
    for (int i = t; i < 64 * 64; i += 256) {
        int o = i >> 6, c = i & 63;
        swT[c * 64 + o] = w[i];
    }
    if (t < 64) {
        sb[t] = bias[t];
        sx[32 * L_LEN + t] = 0.f;
        const float invc = 1.0f / ((float)N_NODES * L_LEN);
        float m   = g_sum[t] * invc;
        float var = g_sq[t] * invc - m * m;
        float sc  = rsqrtf(var + EPS) * g1[t];
        ssc[t] = sc;
        ssh[t] = b1[t] - m * sc;
    }
    int tx = t & 15, ty = t >> 4;
    unsigned int sx_base = smem_u32(sx) + tx * 16;

    ull acc[3][4][2];
#pragma unroll
    for (int a = 0; a < 3; a++)
#pragma unroll
        for (int j = 0; j < 4; j++) { acc[a][j][0] = 0ull; acc[a][j][1] = 0ull; }

    for (int cp = 0; cp < 2; cp++) {
        __syncthreads();
        for (int i = t; i < 32 * L_LEN; i += 256) {
            int ch = cp * 32 + i / L_LEN;
            size_t gidx = (size_t)n * IN_FEATS + cp * 32 * L_LEN + i;
            float raw = io_cnn1[gidx];
            float v = fmaxf(raw * ssc[ch] + ssh[ch], 0.f);
            sx[i] = v;
            io_cnn1[gidx] = v;      // post-BN cnn1 output
        }
        __syncthreads();
#pragma unroll 4
        for (int cc = 0; cc < 32; cc++) {
            float wv[4];
            *(float4*)wv = *(const float4*)&swT[(cp * 32 + cc) * 64 + ty * 4];
            ull w2[4];
#pragma unroll
            for (int j = 0; j < 4; j++) w2[j] = pkdup(wv[j]);
#pragma unroll
            for (int lp = 0; lp < 3; lp++) {
                ull x0, x1;
                lds2w(x0, x1, sx_base + cc * (L_LEN * 4) + lp * 256);
#pragma unroll
                for (int j = 0; j < 4; j++) {
                    ffma2(acc[lp][j][0], w2[j], x0);
                    ffma2(acc[lp][j][1], w2[j], x1);
                }
            }
        }
    }
    // store + per-channel stats partials (conflict-free shfl reduce)
    float ts[4] = {0.f, 0.f, 0.f, 0.f}, tq[4] = {0.f, 0.f, 0.f, 0.f};
#pragma unroll
    for (int lp = 0; lp < 3; lp++) {
        int l0 = lp * 64 + tx * 4;
        if (l0 >= L_LEN) continue;     // only lp==2, tx>=3
#pragma unroll
        for (int j = 0; j < 4; j++) {
            int o = ty * 4 + j;
            float4 v;
            unpk(acc[lp][j][0], v.x, v.y);
            unpk(acc[lp][j][1], v.z, v.w);
            v.x += sb[o]; v.y += sb[o]; v.z += sb[o]; v.w += sb[o];
            *(float4*)&out[(size_t)n * IN_FEATS + o * L_LEN + l0] = v;
            ts[j] += v.x + v.y + v.z + v.w;
            tq[j] += v.x * v.x + v.y * v.y + v.z * v.z + v.w * v.w;
        }
    }
#pragma unroll
    for (int j = 0; j < 4; j++) {
#pragma unroll
        for (int o = 8; o > 0; o >>= 1) {
            ts[j] += __shfl_xor_sync(0xffffffffu, ts[j], o);
            tq[j] += __shfl_xor_sync(0xffffffffu, tq[j], o);
        }
    }
    if (tx == 0) {
#pragma unroll
        for (int j = 0; j < 4; j++) {
            atomicAdd(&g_sum[64 + ty * 4 + j], ts[j]);
            atomicAdd(&g_sq [64 + ty * 4 + j], tq[j]);
        }
    }
}

// ---------------- degree / CSR ----------------
__global__ void deg_kernel(const int* __restrict__ edges) {
    int e = blockIdx.x * blockDim.x + threadIdx.x;
    if (e < N_EDGES) atomicAdd(&g_deg[edges[2 * e + 1]], 1);
}

__global__ __launch_bounds__(1024) void scan_kernel() {
    __shared__ int s[1024];
    const int CHUNK = 10;
    int t = threadIdx.x;
    int base = t * CHUNK;
    int loc[CHUNK];
    int sum = 0;
#pragma unroll
    for (int i = 0; i < CHUNK; i++) {
        int v = (base + i < N_NODES) ? g_deg[base + i] : 0;
        loc[i] = sum; sum += v;
    }
    s[t] = sum;
    __syncthreads();
    for (int d = 1; d < 1024; d <<= 1) {
        int v = (t >= d) ? s[t - d] : 0;
        __syncthreads();
        s[t] += v;
        __syncthreads();
    }
    int prev = t ? s[t - 1] : 0;
#pragma unroll
    for (int i = 0; i < CHUNK; i++) {
        int n = base + i;
        if (n < N_NODES) {
            int o = prev + loc[i];
            g_off[n] = o; g_pos[n] = o;
            g_denom[n] = (float)max(g_deg[n], 1);
        }
    }
    if (t == 1023) g_off[N_NODES] = s[1023];
}

__global__ void csr_fill_kernel(const int* __restrict__ edges) {
    int e = blockIdx.x * blockDim.x + threadIdx.x;
    if (e < N_EDGES) {
        int sN = edges[2 * e], d = edges[2 * e + 1];
        int idx = atomicAdd(&g_pos[d], 1);
        g_csr[idx] = sN;
    }
}

// ---------------- weight transpose + bf16 split: W[K][256]x2 -> Wcat^T[512][K] ----------------
__global__ void wsplit_kernel(const float* __restrict__ ws, const float* __restrict__ wn,
                              __nv_bfloat16* __restrict__ whi,
                              __nv_bfloat16* __restrict__ wlo, int K)
{
    __shared__ float tile[32][33];
    int k0 = blockIdx.x * 32, n0 = blockIdx.y * 32;
    int tx = threadIdx.x, ty = threadIdx.y;   // 32 x 8
#pragma unroll
    for (int r = 0; r < 32; r += 8) {
        int k = k0 + ty + r, n = n0 + tx;
        float v = (n < 256) ? ws[(size_t)k * 256 + n] : wn[(size_t)k * 256 + n - 256];
        tile[ty + r][tx] = v;
    }
    __syncthreads();
#pragma unroll
    for (int r = 0; r < 32; r += 8) {
        int n = n0 + ty + r, k = k0 + tx;
        float v = tile[tx][ty + r];
        __nv_bfloat16 h = __float2bfloat16_rn(v);
        whi[(size_t)n * K + k] = h;
        wlo[(size_t)n * K + k] = __float2bfloat16_rn(v - __bfloat162float(h));
    }
}

// ---------------- HMMA bf16 split GEMM, A-reuse fused, M-tile 96 / 192 threads ----------------
#define MT 96
#define GSTAGE 22528
#define GEMM_SMEM_F (3 * GSTAGE)

__device__ __forceinline__ unsigned int swz(unsigned int base, int row, int kc) {
    return base + row * 64 + ((kc ^ ((row >> 1) & 3)) << 4);
}

__device__ __forceinline__ void fused_issue_load(
    const __nv_bfloat16* __restrict__ Ap,
    const __nv_bfloat16* __restrict__ B0p,
    const __nv_bfloat16* __restrict__ B1p,
    unsigned int sa, unsigned int sb0, unsigned int sb1,
    int m0, int n0, int k0, int K, int tid, bool dual)
{
#pragma unroll
    for (int i = 0; i < 2; i++) {
        int idx = tid + i * 192;
        int row = idx >> 2, cch = idx & 3;
        int rg = m0 + row; if (rg > N_NODES - 1) rg = N_NODES - 1;
        CP16(swz(sa, row, cch), Ap + (size_t)rg * K + k0 + cch * 8);
    }
#pragma unroll
    for (int i = 0; i < 3; i++) {
        int idx = tid + i * 192;
        if (idx < 512) {
            int row = idx >> 2, cch = idx & 3;
            CP16(swz(sb0, row, cch), B0p + (size_t)(n0 + row) * K + k0 + cch * 8);
        }
    }
    if (dual) {
#pragma unroll
        for (int i = 0; i < 3; i++) {
            int idx = tid + i * 192;
            if (idx < 512) {
                int row = idx >> 2, cch = idx & 3;
                CP16(swz(sb1, row, cch), B1p + (size_t)(n0 + row) * K + k0 + cch * 8);
            }
        }
    }
    asm volatile("cp.async.commit_group;");
}

__global__ __launch_bounds__(192, 3) void gemm_mma_kernel(
    const __nv_bfloat16* __restrict__ Ahi, const __nv_bfloat16* __restrict__ Alo,
    const __nv_bfloat16* __restrict__ Bhi, const __nv_bfloat16* __restrict__ Blo,
    float* __restrict__ Cs, float* __restrict__ Cn, int K)
{
    extern __shared__ __align__(1024) char gsm[];
    unsigned int base0 = smem_u32(gsm);
    int tid = threadIdx.x, wid = tid >> 5, lane = tid & 31;
    int m0 = blockIdx.y * MT;
    int n0 = blockIdx.x * 128;         // 0..384 within [ws|wn]
    int wm = (wid % 3) * 32;
    int wn = (wid / 3) * 64;

    unsigned int sa[3], sb0[3], sb1[3];
#pragma unroll
    for (int s = 0; s < 3; s++) {
        sa[s]  = base0 + s * GSTAGE;
        sb0[s] = sa[s] + 6144;
        sb1[s] = sb0[s] + 8192;
    }

    const int KC = K / 32, NCH = 2 * KC;   // KC >= 8 always

    float acc[2][8][4];
#pragma unroll
    for (int i = 0; i < 2; i++)
#pragma unroll
        for (int j = 0; j < 8; j++)
#pragma unroll
            for (int q = 0; q < 4; q++) acc[i][j][q] = 0.f;

    fused_issue_load(Ahi, Bhi, Blo, sa[0], sb0[0], sb1[0], m0, n0, 0,  K, tid, true);
    fused_issue_load(Ahi, Bhi, Blo, sa[1], sb0[1], sb1[1], m0, n0, 32, K, tid, true);

    for (int c = 0; c < NCH; c++) {
        if (c < NCH - 1) asm volatile("cp.async.wait_group 1;");
        else             asm volatile("cp.async.wait_group 0;");
        __syncthreads();
        if (c + 2 < NCH) {
            int cf = c + 2;
            bool p1f = cf < KC;
            int k0f = (p1f ? cf : cf - KC) * 32;
            int sf = cf % 3;
            fused_issue_load(p1f ? Ahi : Alo, Bhi, Blo,
                             sa[sf], sb0[sf], sb1[sf], m0, n0, k0f, K, tid, p1f);
        }
        int s = c % 3;
        bool p1 = c < KC;
        unsigned int sas = sa[s], sb0s = sb0[s], sb1s = sb1[s];
#pragma unroll
        for (int ks = 0; ks < 2; ks++) {
            int kc = ks * 2 + (lane >> 4);
            unsigned int a[2][4], b[4][4];
            LDSM4(a[0], swz(sas, wm + (lane & 15), kc));
            LDSM4(a[1], swz(sas, wm + 16 + (lane & 15), kc));
#pragma unroll
            for (int j = 0; j < 4; j++)
                LDSM4(b[j], swz(sb0s, wn + j * 16 + (lane & 15), kc));
#pragma unroll
            for (int mi = 0; mi < 2; mi++)
#pragma unroll
                for (int j = 0; j < 4; j++) {
                    MMA16816(acc[mi][2 * j],     a[mi], b[j][0], b[j][2]);
                    MMA16816(acc[mi][2 * j + 1], a[mi], b[j][1], b[j][3]);
                }
            if (p1) {
#pragma unroll
                for (int j = 0; j < 4; j++)
                    LDSM4(b[j], swz(sb1s, wn + j * 16 + (lane & 15), kc));
#pragma unroll
                for (int mi = 0; mi < 2; mi++)
#pragma unroll
                    for (int j = 0; j < 4; j++) {
                        MMA16816(acc[mi][2 * j],     a[mi], b[j][0], b[j][2]);
                        MMA16816(acc[mi][2 * j + 1], a[mi], b[j][1], b[j][3]);
                    }
            }
        }
    }

    // epilogue
    float* Cout = (n0 < 256) ? Cs : Cn;
    int ncol0 = n0 & 255;
    int g = lane >> 2, tq = lane & 3;
#pragma unroll
    for (int mi = 0; mi < 2; mi++) {
        int r0 = m0 + wm + mi * 16 + g;
#pragma unroll
        for (int j = 0; j < 8; j++) {
            int col = ncol0 + wn + j * 8 + tq * 2;
            if (r0 < N_NODES)
                *(float2*)&Cout[(size_t)r0 * 256 + col] =
                    make_float2(acc[mi][j][0], acc[mi][j][1]);
            if (r0 + 8 < N_NODES)
                *(float2*)&Cout[(size_t)(r0 + 8) * 256 + col] =
                    make_float2(acc[mi][j][2], acc[mi][j][3]);
        }
    }
}

// ---------------- fp32 SIMT GEMM (MLP head only) ----------------
__global__ __launch_bounds__(256, 2) void gemm2_kernel(
    const float* __restrict__ A,
    const float* __restrict__ B0, const float* __restrict__ B1,
    float* __restrict__ C0, float* __restrict__ C1,
    int M, int Nc, int K, int nxHalf)
{
    __shared__ float As[8][264];
    __shared__ float Bs[8][132];
    int bx = blockIdx.x;
    const float* B = B0;
    float* C = C0;
    if (bx >= nxHalf) { B = B1; C = C1; bx -= nxHalf; }
    int tid = threadIdx.x;
    int m0 = blockIdx.y * 128, n0 = bx * 128;
    int tx = tid & 15, ty = tid >> 4;

    ull acc[8][4];
#pragma unroll
    for (int i = 0; i < 8; i++)
#pragma unroll
        for (int j = 0; j < 4; j++) acc[i][j] = 0ull;

    int a_row = tid >> 1, a_col = (tid & 1) * 4;
    int b_row = tid >> 5, b_col = (tid & 31) * 4;
    bool a_ok = (m0 + a_row) < M;
    bool b_ok = (n0 + b_col) < Nc;
    const float* Abase = A + (size_t)(m0 + a_row) * K + a_col;
    const float* Bbase = B + n0 + b_col;

    unsigned int as0 = smem_u32(As);
    unsigned int bs0 = smem_u32(Bs);
    unsigned int as_w = as0 + a_col * (264 * 4) + a_row * 8;
    unsigned int as_r = as0 + ty * 32;
    unsigned int bs_r = bs0 + tx * 16;

    for (int k0 = 0; k0 < K; k0 += 8) {
        float4 av = a_ok ? *(const float4*)(Abase + k0) : make_float4(0, 0, 0, 0);
        float4 bv = b_ok ? *(const float4*)(Bbase + (size_t)(k0 + b_row) * Nc)
                         : make_float4(0, 0, 0, 0);
        __syncthreads();
        sts64(as_w + 0 * 1056, pkdup(av.x));
        sts64(as_w + 1 * 1056, pkdup(av.y));
        sts64(as_w + 2 * 1056, pkdup(av.z));
        sts64(as_w + 3 * 1056, pkdup(av.w));
        *(float4*)&Bs[b_row][b_col] = bv;
        __syncthreads();
#pragma unroll
        for (int kk = 0; kk < 8; kk++) {
            ull a2[8], b2[4];
            unsigned int ar = as_r + kk * 1056;
            unsigned int br = bs_r + kk * 528;
            lds2w(a2[0], a2[1], ar);
            lds2w(a2[2], a2[3], ar + 16);
            lds2w(a2[4], a2[5], ar + 512);
            lds2w(a2[6], a2[7], ar + 528);
            lds2w(b2[0], b2[1], br);
            lds2w(b2[2], b2[3], br + 256);
#pragma unroll
            for (int i = 0; i < 8; i++)
#pragma unroll
                for (int j = 0; j < 4; j++) ffma2(acc[i][j], a2[i], b2[j]);
        }
    }
#pragma unroll
    for (int bi = 0; bi < 2; bi++)
#pragma unroll
        for (int i = 0; i < 4; i++) {
            int r = m0 + bi * 64 + ty * 4 + i;
            if (r >= M) continue;
            int i8 = bi * 4 + i;
#pragma unroll
            for (int bj = 0; bj < 2; bj++) {
                int c = n0 + bj * 64 + tx * 4;
                if (c >= Nc) continue;
                float4 v;
                unpk(acc[i8][2 * bj + 0], v.x, v.y);
                unpk(acc[i8][2 * bj + 1], v.z, v.w);
                *(float4*)&C[(size_t)r * Nc + c] = v;
            }
        }
}

// ---------------- neighbor gather (CSR) + combine, float4 channels ----------------
// One block (64 threads) per node; thread t owns channels 4t..4t+3.
__global__ __launch_bounds__(64) void neigh_combine_kernel(
    const float4* __restrict__ hn, const float4* __restrict__ hs,
    const float4* __restrict__ bias, float4* __restrict__ h2)
{
    int n = blockIdx.x, t = threadIdx.x;
    __shared__ int sidx[64];
    int s0 = g_off[n], s1 = g_off[n + 1];
    float4 acc = make_float4(0.f, 0.f, 0.f, 0.f);
    for (int base = s0; base < s1; base += 64) {
        int cnt = min(64, s1 - base);
        __syncthreads();
        if (t < cnt) sidx[t] = g_csr[base + t];
        __syncthreads();
        for (int j = 0; j < cnt; j++) {
            float4 v = hn[(size_t)sidx[j] * (HID / 4) + t];
            acc.x += v.x; acc.y += v.y; acc.z += v.z; acc.w += v.w;
        }
    }
    float inv = 1.0f / g_denom[n];
    float4 hv = hs[(size_t)n * (HID / 4) + t];
    float4 bv = bias[t];
    float4 r;
    r.x = hv.x + acc.x * inv + bv.x;
    r.y = hv.y + acc.y * inv + bv.y;
    r.z = hv.z + acc.z * inv + bv.z;
    r.w = hv.w + acc.w * inv + bv.w;
    h2[(size_t)n * (HID / 4) + t] = r;
}

// ---------------- per-column stats ----------------
__global__ void col_stats_kernel(const float* __restrict__ x, int rows) {
    int c = threadIdx.x, cols = blockDim.x;
    float s = 0.f, q = 0.f;
    for (int r = blockIdx.x; r < rows; r += gridDim.x) {
        float v = x[(size_t)r * cols + c];
        s += v; q += v * v;
    }
    atomicAdd(&g_sum[c], s);
    atomicAdd(&g_sq[c],  q);
}

// ---------------- node BN + residual + relu (float4); optional bf16 split out ----------------
__global__ void bn_apply_kernel(
    const float4* __restrict__ x, const float4* __restrict__ pre,
    float4* __restrict__ outp, float4* __restrict__ aux,
    const float* __restrict__ gam, const float* __restrict__ bet,
    __nv_bfloat162* __restrict__ ahi, __nv_bfloat162* __restrict__ alo)
{
    const float invn = 1.0f / (float)N_NODES;
    const int total4 = N_NODES * (HID / 4);
    for (int idx = blockIdx.x * blockDim.x + threadIdx.x; idx < total4;
         idx += gridDim.x * blockDim.x) {
        int c0 = (idx & (HID / 4 - 1)) * 4;
        float sc[4], sh[4];
#pragma unroll
        for (int i = 0; i < 4; i++) {
            float m   = g_sum[c0 + i] * invn;
            float var = g_sq[c0 + i] * invn - m * m;
            sc[i] = rsqrtf(var + EPS) * gam[c0 + i];
            sh[i] = bet[c0 + i] - m * sc[i];
        }
        float4 v = x[idx];
        v.x = v.x * sc[0] + sh[0];
        v.y = v.y * sc[1] + sh[1];
        v.z = v.z * sc[2] + sh[2];
        v.w = v.w * sc[3] + sh[3];
        if (pre) {
            float4 p = pre[idx];
            v.x += p.x; v.y += p.y; v.z += p.z; v.w += p.w;
        }
        v.x = fmaxf(v.x, 0.f);
        v.y = fmaxf(v.y, 0.f);
        v.z = fmaxf(v.z, 0.f);
        v.w = fmaxf(v.w, 0.f);
        outp[idx] = v;
        if (aux) aux[idx] = v;
        if (ahi) {
            __nv_bfloat16 hx = __float2bfloat16_rn(v.x);
            __nv_bfloat16 hy = __float2bfloat16_rn(v.y);
            __nv_bfloat16 hz = __float2bfloat16_rn(v.z);
            __nv_bfloat16 hw = __float2bfloat16_rn(v.w);
            ahi[2 * idx]     = __nv_bfloat162{hx, hy};
            ahi[2 * idx + 1] = __nv_bfloat162{hz, hw};
            alo[2 * idx] = __nv_bfloat162{
                __float2bfloat16_rn(v.x - __bfloat162float(hx)),
                __float2bfloat16_rn(v.y - __bfloat162float(hy))};
            alo[2 * idx + 1] = __nv_bfloat162{
                __float2bfloat16_rn(v.z - __bfloat162float(hz)),
                __float2bfloat16_rn(v.w - __bfloat162float(hw))};
        }
    }
}

// ---------------- MLP head ----------------
__global__ __launch_bounds__(128) void mlp_out_kernel(
    const float* __restrict__ z, const float* __restrict__ gam,
    const float* __restrict__ bet, const float* __restrict__ w2,
    const float* __restrict__ b2, float* __restrict__ out)
{
    __shared__ float sm[64], si[64], sg[64], sb[64], sw[128], sb2[2];
    int t = threadIdx.x;
    if (t < 64) {
        float m   = g_sum[t] / (float)N_NODES;
        float var = g_sq[t] / (float)N_NODES - m * m;
        sm[t] = m;
        si[t] = rsqrtf(var + EPS);
        sg[t] = gam[t];
        sb[t] = bet[t];
    }
    if (t < 128) sw[t] = w2[t];
    if (t < 2)   sb2[t] = b2[t];
    __syncthreads();
    int n = blockIdx.x * 128 + t;
    if (n < N_NODES) {
        float a0 = sb2[0], a1 = sb2[1];
        const float* zr = z + (size_t)n * 64;
#pragma unroll
        for (int j = 0; j < 64; j++) {
            float v = (zr[j] - sm[j]) * si[j] * sg[j] + sb[j];
            v = fmaxf(v, 0.f);
            a0 += v * sw[2 * j];
            a1 += v * sw[2 * j + 1];
        }
        out[2 * n]     = a0;
        out[2 * n + 1] = a1;
    }
}

// ---------------- host ----------------
extern "C" void kernel_launch(void* const* d_in, const int* in_sizes, int n_in,
                              void* d_out, int out_size)
{
    const float* inputs  = (const float*)d_in[0];
    const float* conv1_w = (const float*)d_in[1];
    const float* conv1_b = (const float*)d_in[2];
    const float* bn_c1_g = (const float*)d_in[3];
    const float* bn_c1_b = (const float*)d_in[4];
    const float* conv2_w = (const float*)d_in[5];
    const float* conv2_b = (const float*)d_in[6];
    const float* bn_c2_g = (const float*)d_in[7];
    const float* bn_c2_b = (const float*)d_in[8];
    const float* ws0     = (const float*)d_in[9];
    const float* wn0     = (const float*)d_in[10];
    const float* b0      = (const float*)d_in[11];
    const float* ws_rest = (const float*)d_in[12];
    const float* wn_rest = (const float*)d_in[13];
    const float* b_rest  = (const float*)d_in[14];
    const float* bn_g    = (const float*)d_in[15];
    const float* bn_b    = (const float*)d_in[16];
    const float* mlp_w1  = (const float*)d_in[17];
    // d_in[18] = mlp_b1 : constant shift, cancels exactly inside batchnorm
    const float* mlp_bn_g = (const float*)d_in[19];
    const float* mlp_bn_b = (const float*)d_in[20];
    const float* mlp_w2   = (const float*)d_in[21];
    const float* mlp_b2   = (const float*)d_in[22];
    const int*   edges    = (const int*)d_in[23];

    float* out  = (float*)d_out;
    float* cnn1 = out + CNN1_OFF;
    float* cnn2 = out + CNN2_OFF;
    float* fin  = out + FIN_OFF;

    float *hb, *h2b, *hnb, *hsb, *zb;
    __nv_bfloat16 *ahib, *alob, *whib, *wlob;
    cudaGetSymbolAddress((void**)&hb,   g_h);
    cudaGetSymbolAddress((void**)&h2b,  g_h2);
    cudaGetSymbolAddress((void**)&hnb,  g_hn);
    cudaGetSymbolAddress((void**)&hsb,  g_hs);
    cudaGetSymbolAddress((void**)&zb,   g_z);
    cudaGetSymbolAddress((void**)&ahib, g_Ahi);
    cudaGetSymbolAddress((void**)&alob, g_Alo);
    cudaGetSymbolAddress((void**)&whib, g_Whi);
    cudaGetSymbolAddress((void**)&wlob, g_Wlo);

    cudaFuncSetAttribute(gemm_mma_kernel,
                         cudaFuncAttributeMaxDynamicSharedMemorySize, GEMM_SMEM_F);

    // ---- weight transpose + split ----
    wsplit_kernel<<<dim3(IN_FEATS / 32, 16), dim3(32, 8)>>>(ws0, wn0, whib, wlob, IN_FEATS);
    for (int l = 1; l < 4; l++) {
        wsplit_kernel<<<dim3(HID / 32, 16), dim3(32, 8)>>>(
            ws_rest + (size_t)(l - 1) * HID * HID,
            wn_rest + (size_t)(l - 1) * HID * HID,
            whib + W_L0_ELEMS + (size_t)(l - 1) * W_REST_ELEMS,
            wlob + W_L0_ELEMS + (size_t)(l - 1) * W_REST_ELEMS, HID);
    }

    // ---- CNN front-end ----
    // stats: conv1 -> g_sum[0..64) (fused, warp-per-channel);
    //        conv2 -> g_sum[64..128) (fused, shfl-reduced)
    zero_stats_kernel<<<1, 256>>>();
    conv1_kernel<<<N_NODES, 256>>>(inputs, conv1_w, conv1_b, cnn1);
    conv2_kernel<<<N_NODES, 256>>>(cnn1, conv2_w, conv2_b, bn_c1_g, bn_c1_b, cnn2);
    bn_chan_apply_kernel<<<8192, 256>>>((float4*)cnn2, (const float4*)cnn1,
                                        bn_c2_g, bn_c2_b,
                                        (__nv_bfloat162*)ahib, (__nv_bfloat162*)alob, 64);

    // ---- degree + CSR ----
    zero_deg_kernel<<<(N_NODES + 255) / 256, 256>>>();
    deg_kernel<<<(N_EDGES + 255) / 256, 256>>>(edges);
    scan_kernel<<<1, 1024>>>();
    csr_fill_kernel<<<(N_EDGES + 255) / 256, 256>>>(edges);

    // ---- 4 GraphSAGE layers (HMMA split-bf16 GEMMs, A-reuse fused, M96 tiles) ----
    for (int l = 0; l < 4; l++) {
        int K = (l == 0) ? IN_FEATS : HID;
        const __nv_bfloat16* wh =
            whib + ((l == 0) ? 0 : W_L0_ELEMS + (size_t)(l - 1) * W_REST_ELEMS);
        const __nv_bfloat16* wl =
            wlob + ((l == 0) ? 0 : W_L0_ELEMS + (size_t)(l - 1) * W_REST_ELEMS);
        const float* bb = (l == 0) ? b0 : b_rest + (size_t)(l - 1) * HID;

        gemm_mma_kernel<<<dim3(4, (N_NODES + MT - 1) / MT), 192, GEMM_SMEM_F>>>(
            ahib, alob, wh, wl, hsb, hnb, K);

        neigh_combine_kernel<<<N_NODES, 64>>>(
            (const float4*)hnb, (const float4*)hsb, (const float4*)bb, (float4*)h2b);

        zero_stats_kernel<<<1, 256>>>();
        col_stats_kernel<<<512, HID>>>(h2b, N_NODES);
        bn_apply_kernel<<<2560, 256>>>(
            (const float4*)h2b, (l > 0) ? (const float4*)hb : nullptr,
            (float4*)hb, (l == 3) ? (float4*)fin : nullptr,
            bn_g + (size_t)l * HID, bn_b + (size_t)l * HID,
            (l < 3) ? (__nv_bfloat162*)ahib : nullptr,
            (l < 3) ? (__nv_bfloat162*)alob : nullptr);
    }

    // ---- MLP head ----
    {
        dim3 grid(1, 79);
        gemm2_kernel<<<grid, 256>>>(hb, mlp_w1, mlp_w1, zb, zb, N_NODES, C_MID, HID, 1);
        zero_stats_kernel<<<1, 256>>>();
        col_stats_kernel<<<2048, C_MID>>>(zb, N_NODES);
        mlp_out_kernel<<<(N_NODES + 127) / 128, 128>>>(
            zb, mlp_bn_g, mlp_bn_b, mlp_w2, mlp_b2, out);
    }
}